// round 15
// baseline (speedup 1.0000x reference)
#include <cuda_runtime.h>
#include <math.h>

#define BATCH 32
#define NMEM 512
#define NW 8
#define QL 32
#define NC 8
#define CL 8
#define VOCAB 50000
#define EM 256
#define D 768
#define D4 192          // D / 4
#define D2 384          // D / 2
#define NVEC 9          // vec 0 = question, vec 1..8 = answer choices
#define MCH 8           // m-chunks (64 m each) in o-accumulation
#define EK 8            // split-K factor in matvec (e-chunks of 96)
#define VS (NVEC * BATCH * D)   // one vec-set in floats

// ---------------- device scratch (static: no allocations allowed) ----------
__device__ float g_E[2 * BATCH * NMEM * D];        // 100MB: tables 1,2 (slot = t-1)
__device__ float g_ua[NVEC * BATCH * D];           // rows: r = v*32+b  (u then a)
__device__ float g_vec[NVEC * BATCH * D];          // reduced Uu / Va
__device__ float g_vp[EK * NVEC * BATCH * D];      // matvec split-K partials
__device__ float g_sc[NVEC * BATCH * NMEM];        // scores, then p in place
__device__ float g_op[MCH * NVEC * BATCH * D];     // partial o sums
__device__ float g_o[NVEC * BATCH * D];            // o_q (v=0), o_a (v=1..8)
__device__ float g_qw[BATCH * D];                  // o_q^T W

// ---------------- kernels ---------------------------------------------------

// Materialize E for one table (slot z, table z+1).
// 192 threads: f = tid/64 field, d4 = tid%64 float4 lane; 8 LDG.128 per thread.
__global__ void __launch_bounds__(192) k_embed(
        const int* __restrict__ subj, const int* __restrict__ rel,
        const int* __restrict__ obj, const float* __restrict__ A, int z) {
    __shared__ int sidx[24];
    int m = blockIdx.x, b = blockIdx.y;
    int tid = threadIdx.x;
    if (tid < 24) {
        const int* src = (tid < 8) ? subj : (tid < 16 ? rel : obj);
        sidx[tid] = __ldg(src + (b * NMEM + m) * NW + (tid & 7));
    }
    __syncthreads();
    int f = tid >> 6;            // 0,1,2
    int d4 = tid & 63;           // 0..63
    const float4* tab4 = (const float4*)(A + (size_t)(z + 1) * VOCAB * EM);
    float4 acc = make_float4(0.f, 0.f, 0.f, 0.f);
#pragma unroll
    for (int w = 0; w < NW; w++) {
        float4 v = __ldg(tab4 + (size_t)sidx[f * NW + w] * 64 + d4);
        acc.x += v.x; acc.y += v.y; acc.z += v.z; acc.w += v.w;
    }
    float4* e4 = (float4*)(g_E + ((size_t)(z * BATCH + b) * NMEM + m) * D);
    e4[f * 64 + d4] = acc;
}

// Fused hop-0 scores: gather table 0, field-at-a-time, coalesced lane mapping.
__global__ void __launch_bounds__(256, 6) k_gscore(
        const int* __restrict__ subj, const int* __restrict__ rel,
        const int* __restrict__ obj, const float* __restrict__ A) {
    __shared__ __align__(16) float sv[NVEC * D];   // 27 KB
    __shared__ int sidx[8 * 24];
    int b = blockIdx.y, mc = blockIdx.x;           // 8 m per block
    for (int i = threadIdx.x; i < NVEC * D; i += 256) {
        int v = i / D, d = i - v * D;
        sv[i] = g_vec[(size_t)(v * BATCH + b) * D + d];
    }
    if (threadIdx.x < 192) {
        int m_l = threadIdx.x / 24, which = threadIdx.x % 24;
        int f = which >> 3, w = which & 7;
        const int* src = (f == 0) ? subj : (f == 1 ? rel : obj);
        sidx[threadIdx.x] = __ldg(src + (size_t)(b * NMEM + mc * 8 + m_l) * NW + w);
    }
    __syncthreads();
    int warp = threadIdx.x >> 5, lane = threadIdx.x & 31;
    int m = mc * 8 + warp;
    const int* idx = &sidx[warp * 24];
    const float4* T4 = (const float4*)A;           // table 0

    float acc[NVEC];
#pragma unroll
    for (int v = 0; v < NVEC; v++) acc[v] = 0.f;

#pragma unroll
    for (int f = 0; f < 3; f++) {
        float4 s0 = make_float4(0.f, 0.f, 0.f, 0.f);
        float4 s1 = make_float4(0.f, 0.f, 0.f, 0.f);
#pragma unroll
        for (int w = 0; w < NW; w++) {
            const float4* r4 = T4 + (size_t)idx[f * 8 + w] * 64;
            float4 x0 = __ldg(r4 + lane);
            float4 x1 = __ldg(r4 + 32 + lane);
            s0.x += x0.x; s0.y += x0.y; s0.z += x0.z; s0.w += x0.w;
            s1.x += x1.x; s1.y += x1.y; s1.z += x1.z; s1.w += x1.w;
        }
#pragma unroll
        for (int v = 0; v < NVEC; v++) {
            const float4* s4 = (const float4*)&sv[v * D + f * EM];
            float4 a0 = s4[lane], a1 = s4[32 + lane];
            acc[v] += s0.x * a0.x + s0.y * a0.y + s0.z * a0.z + s0.w * a0.w
                    + s1.x * a1.x + s1.y * a1.y + s1.z * a1.z + s1.w * a1.w;
        }
    }
#pragma unroll
    for (int v = 0; v < NVEC; v++) {
        float x = acc[v];
#pragma unroll
        for (int off = 16; off; off >>= 1)
            x += __shfl_down_sync(0xffffffffu, x, off);
        if (lane == 0)
            g_sc[(size_t)(v * BATCH + b) * NMEM + m] = x;
    }
}

// u[b] = sum_q B[ques];  a[c][b] = sum_w B[answerChoices]  (float4, 192 thr)
__global__ void k_init_ua(const int* __restrict__ ques, const int* __restrict__ ac,
                          const float* __restrict__ Bt) {
    int v = blockIdx.x;            // 0..31 = u rows, 32..287 = a rows (r = 32+c*32+b)
    int d4 = threadIdx.x;          // 0..191
    const float4* B4 = (const float4*)Bt;
    float4 acc = make_float4(0.f, 0.f, 0.f, 0.f);
    if (v < BATCH) {
        for (int q = 0; q < QL; q++) {
            int row = __ldg(ques + v * QL + q);
            float4 x = __ldg(B4 + (size_t)row * D4 + d4);
            acc.x += x.x; acc.y += x.y; acc.z += x.z; acc.w += x.w;
        }
    } else {
        int idx = v - BATCH;
        int c = idx >> 5, b = idx & 31;
        for (int w = 0; w < CL; w++) {
            int row = __ldg(ac + (b * NC + c) * CL + w);
            float4 x = __ldg(B4 + (size_t)row * D4 + d4);
            acc.x += x.x; acc.y += x.y; acc.z += x.z; acc.w += x.w;
        }
    }
    ((float4*)g_ua)[(size_t)v * D4 + d4] = acc;
}

// split-K matvec partial, register-tiled 4r x 2c per thread, float2 inner loop.
// g_vp[ek][r][d] = sum_{e in chunk of 96} X[r][e] * M[d][e]
// grid (12 col-tiles of 64, 9 row-tiles of 32, EK)
__global__ void __launch_bounds__(256, 6) k_matvec(
        const float* __restrict__ U, const float* __restrict__ V) {
    __shared__ float2 sX2[32][17];    // 32 rows x 16 float2 (e-major), pad 1
    __shared__ float2 sM2[64][17];    // 64 cols x 16 float2 (e-major), pad 1
    int ct = blockIdx.x;           // 0..11 (64 cols)
    int rt = blockIdx.y;           // 0..8  (32 rows)
    int ek = blockIdx.z;           // 0..EK-1 (96 e)
    const float* M = (rt == 0) ? U : V;
    int tid = threadIdx.x;
    int tx = tid & 31, ty = tid >> 5;   // 32 x 8
    float acc[4][2];
#pragma unroll
    for (int i = 0; i < 4; i++) { acc[i][0] = 0.f; acc[i][1] = 0.f; }
    int eBeg = ek * (D / EK), eEnd = eBeg + (D / EK);
    for (int e0 = eBeg; e0 < eEnd; e0 += 32) {
        // fill sX: 32 rows x 16 float2 = 512 f2, 2 per thread
#pragma unroll
        for (int k = 0; k < 2; k++) {
            int idx = k * 256 + tid;
            int row = idx >> 4, e2 = idx & 15;
            sX2[row][e2] = *(const float2*)&g_ua[(size_t)(rt * 32 + row) * D + e0 + e2 * 2];
        }
        // fill sM: 64 cols x 16 float2 = 1024 f2, 4 per thread
#pragma unroll
        for (int k = 0; k < 4; k++) {
            int idx = k * 256 + tid;
            int col = idx >> 4, e2 = idx & 15;
            sM2[col][e2] = *(const float2*)&M[(size_t)(ct * 64 + col) * D + e0 + e2 * 2];
        }
        __syncthreads();
#pragma unroll
        for (int e2 = 0; e2 < 16; e2++) {
            float2 m0 = sM2[tx][e2], m1 = sM2[tx + 32][e2];
#pragma unroll
            for (int i = 0; i < 4; i++) {
                float2 xv = sX2[ty * 4 + i][e2];
                acc[i][0] += xv.x * m0.x + xv.y * m0.y;
                acc[i][1] += xv.x * m1.x + xv.y * m1.y;
            }
        }
        __syncthreads();
    }
    float* vp = g_vp + (size_t)ek * VS;
#pragma unroll
    for (int i = 0; i < 4; i++) {
        size_t row = rt * 32 + ty * 4 + i;
        vp[row * D + ct * 64 + tx]      = acc[i][0];
        vp[row * D + ct * 64 + 32 + tx] = acc[i][1];
    }
}

// reduce split-K partials: g_vec = sum_ek g_vp[ek]
__global__ void k_vred() {
    const int S = NVEC * BATCH * D4;       // float4 units (55296)
    int i = blockIdx.x * 256 + threadIdx.x;
    if (i >= S) return;
    const float4* vp4 = (const float4*)g_vp;
    float4 r = vp4[i];
#pragma unroll
    for (int k = 1; k < EK; k++) {
        float4 x = vp4[(size_t)k * S + i];
        r.x += x.x; r.y += x.y; r.z += x.z; r.w += x.w;
    }
    ((float4*)g_vec)[i] = r;
}

// hop-1 scores from materialized E (slot 0): 2 m per warp, float4 loads
__global__ void __launch_bounds__(256, 6) k_scores(int slot) {
    __shared__ __align__(16) float4 sv4[NVEC * D4];   // 27 KB
    int b = blockIdx.y;
    const float4* gv4 = (const float4*)g_vec;
    for (int i = threadIdx.x; i < NVEC * D4; i += 256) {
        int v = i / D4, d4 = i - v * D4;
        sv4[i] = gv4[(size_t)(v * BATCH + b) * D4 + d4];
    }
    __syncthreads();
    int warp = threadIdx.x >> 5, lane = threadIdx.x & 31;
    int m0 = blockIdx.x * 16 + warp * 2;
    const float4* e0 = (const float4*)(g_E + ((size_t)(slot * BATCH + b) * NMEM + m0) * D);
    const float4* e1 = e0 + D4;
    float acc[NVEC][2];
#pragma unroll
    for (int v = 0; v < NVEC; v++) { acc[v][0] = 0.f; acc[v][1] = 0.f; }
#pragma unroll
    for (int k = 0; k < 6; k++) {
        int d4 = lane + 32 * k;
        float4 x0 = __ldg(e0 + d4);
        float4 x1 = __ldg(e1 + d4);
#pragma unroll
        for (int v = 0; v < NVEC; v++) {
            float4 s = sv4[v * D4 + d4];
            acc[v][0] += x0.x * s.x + x0.y * s.y + x0.z * s.z + x0.w * s.w;
            acc[v][1] += x1.x * s.x + x1.y * s.y + x1.z * s.z + x1.w * s.w;
        }
    }
#pragma unroll
    for (int v = 0; v < NVEC; v++) {
#pragma unroll
        for (int i = 0; i < 2; i++) {
            float x = acc[v][i];
#pragma unroll
            for (int off = 16; off; off >>= 1)
                x += __shfl_down_sync(0xffffffffu, x, off);
            if (lane == 0)
                g_sc[(size_t)(v * BATCH + b) * NMEM + m0 + i] = x;
        }
    }
}

// block reduce over 512 threads via shuffles: mode 0 sum, 1 max, 2 min
__device__ __forceinline__ float bred512(float v, int mode, float* sw) {
    int lane = threadIdx.x & 31, w = threadIdx.x >> 5;
#pragma unroll
    for (int off = 16; off; off >>= 1) {
        float o = __shfl_xor_sync(0xffffffffu, v, off);
        v = (mode == 0) ? v + o : (mode == 1) ? fmaxf(v, o) : fminf(v, o);
    }
    if (lane == 0) sw[w] = v;
    __syncthreads();
    if (w == 0) {
        float x;
        if (mode == 0)      x = (lane < 16) ? sw[lane] : 0.f;
        else if (mode == 1) x = (lane < 16) ? sw[lane] : -INFINITY;
        else                x = (lane < 16) ? sw[lane] : INFINITY;
#pragma unroll
        for (int off = 16; off; off >>= 1) {
            float o = __shfl_xor_sync(0xffffffffu, x, off);
            x = (mode == 0) ? x + o : (mode == 1) ? fmaxf(x, o) : fminf(x, o);
        }
        if (lane == 0) sw[0] = x;
    }
    __syncthreads();
    float r = sw[0];
    __syncthreads();
    return r;
}

// merged renorm: rows 0..31 = question variant, 32..287 = answer variant
__global__ void k_renorm() {
    __shared__ float sw[16];
    int r = blockIdx.x;            // 0..287, row = v*BATCH+b
    int m = threadIdx.x;
    size_t base = (size_t)r * NMEM;
    float s = g_sc[base + m];
    float mx = bred512(s, 1, sw);
    float se = bred512(expf(s - mx), 0, sw);
    float p = s - mx - logf(se);
    if (r < BATCH) {
        float mn = bred512(p, 2, sw);
        p -= mn;
        float nrm = bred512(fabsf(p + 1e-8f), 0, sw);
        g_sc[base + m] = p / nrm;
    } else {
        float nrm = bred512(fabsf(p), 0, sw);
        float p2 = (nrm == 0.f) ? (p + 1.f) : p;
        float nrm2 = bred512(fabsf(p2), 0, sw);
        g_sc[base + m] = p2 / nrm2;
    }
}

// partial o sums: g_op[mc][v][b][:] = sum_{m in 64-chunk} p[v][b][m] * E[slot][b][m][:]
__global__ void k_oacc(int slot) {
    __shared__ float sp[NVEC * 64];
    int b = blockIdx.x, mc = blockIdx.y, dc = blockIdx.z;
    for (int i = threadIdx.x; i < NVEC * 64; i += 192) {
        int v = i >> 6, ml = i & 63;
        sp[i] = g_sc[(size_t)(v * BATCH + b) * NMEM + mc * 64 + ml];
    }
    __syncthreads();
    int d2 = dc * 192 + threadIdx.x;
    const float2* e = (const float2*)(g_E + ((size_t)(slot * BATCH + b) * NMEM + mc * 64) * D);
    float2 acc[NVEC];
#pragma unroll
    for (int v = 0; v < NVEC; v++) acc[v] = make_float2(0.f, 0.f);
#pragma unroll 4
    for (int ml = 0; ml < 64; ml++) {
        float2 ev = __ldg(e + (size_t)ml * D2 + d2);
#pragma unroll
        for (int v = 0; v < NVEC; v++) {
            float p = sp[v * 64 + ml];
            acc[v].x += ev.x * p; acc[v].y += ev.y * p;
        }
    }
    float2* op2 = (float2*)g_op;
#pragma unroll
    for (int v = 0; v < NVEC; v++)
        op2[(size_t)((mc * NVEC + v) * BATCH + b) * D2 + d2] = acc[v];
}

// o = sum of MCH partials; u/a += o
__global__ void k_update() {
    const int S = NVEC * BATCH * D4;       // in float4 units
    int i = blockIdx.x * 256 + threadIdx.x;
    if (i >= S) return;
    const float4* op4 = (const float4*)g_op;
    float4 o = make_float4(0.f, 0.f, 0.f, 0.f);
#pragma unroll
    for (int k = 0; k < MCH; k++) {
        float4 x = op4[(size_t)k * S + i];
        o.x += x.x; o.y += x.y; o.z += x.z; o.w += x.w;
    }
    ((float4*)g_o)[i] = o;
    float4 u = ((float4*)g_ua)[i];
    u.x += o.x; u.y += o.y; u.z += o.z; u.w += o.w;
    ((float4*)g_ua)[i] = u;
}

// qw[b][e] = sum_d o_q[b][d] * W[d][e]   (tiled: W read once)
__global__ void k_qw(const float* __restrict__ W) {
    __shared__ float sQ[32][33];
    __shared__ float sW[32][33];
    int et = blockIdx.x;           // 0..23
    int tx = threadIdx.x & 31, ty = threadIdx.x >> 5;   // 32 x 8
    float acc[4] = {0.f, 0.f, 0.f, 0.f};
    for (int d0 = 0; d0 < D; d0 += 32) {
#pragma unroll
        for (int i = 0; i < 4; i++) {
            int row = ty * 4 + i;
            sQ[row][tx] = g_o[(size_t)row * D + d0 + tx];          // b = row
            sW[row][tx] = __ldg(W + (size_t)(d0 + row) * D + et * 32 + tx);
        }
        __syncthreads();
#pragma unroll
        for (int k = 0; k < 32; k++) {
            float wv = sW[k][tx];
#pragma unroll
            for (int i = 0; i < 4; i++) acc[i] += sQ[ty * 4 + i][k] * wv;
        }
        __syncthreads();
    }
#pragma unroll
    for (int i = 0; i < 4; i++)
        g_qw[(size_t)(ty * 4 + i) * D + et * 32 + tx] = acc[i];
}

// pred[b][c] = qW[b] . o_a[c][b]
__global__ void k_pred(float* __restrict__ out) {
    __shared__ float sh[256];
    int b = blockIdx.x, c = blockIdx.y;
    int t = threadIdx.x;
    const float* q = g_qw + (size_t)b * D;
    const float* oa = g_o + (size_t)((1 + c) * BATCH + b) * D;
    float acc = 0.f;
    for (int e = t; e < D; e += 256) acc += q[e] * oa[e];
    sh[t] = acc;
    __syncthreads();
    for (int s = 128; s > 0; s >>= 1) {
        if (t < s) sh[t] += sh[t + s];
        __syncthreads();
    }
    if (t == 0) out[b * NC + c] = sh[0];
}

// ---------------- launch ----------------------------------------------------
static cudaStream_t g_s2 = 0;
static cudaEvent_t  g_evFork = 0, g_evJoin0 = 0, g_evJoin1 = 0;

extern "C" void kernel_launch(void* const* d_in, const int* in_sizes, int n_in,
                              void* d_out, int out_size) {
    const int*   subj = (const int*)d_in[0];
    const int*   rel  = (const int*)d_in[1];
    const int*   obj  = (const int*)d_in[2];
    const int*   ques = (const int*)d_in[3];
    const int*   ac   = (const int*)d_in[4];
    const float* A    = (const float*)d_in[5];
    const float* Bt   = (const float*)d_in[6];
    const float* U    = (const float*)d_in[7];
    const float* V    = (const float*)d_in[8];
    const float* W    = (const float*)d_in[9];
    float* out = (float*)d_out;

    if (!g_s2) {
        cudaStreamCreateWithFlags(&g_s2, cudaStreamNonBlocking);
        cudaEventCreateWithFlags(&g_evFork, cudaEventDisableTiming);
        cudaEventCreateWithFlags(&g_evJoin0, cudaEventDisableTiming);
        cudaEventCreateWithFlags(&g_evJoin1, cudaEventDisableTiming);
    }

    // Fork: embed table 1 then table 2 on the side stream.
    cudaEventRecord(g_evFork, 0);
    cudaStreamWaitEvent(g_s2, g_evFork, 0);
    k_embed<<<dim3(NMEM, BATCH), 192, 0, g_s2>>>(subj, rel, obj, A, 0);
    cudaEventRecord(g_evJoin0, g_s2);
    k_embed<<<dim3(NMEM, BATCH), 192, 0, g_s2>>>(subj, rel, obj, A, 1);
    cudaEventRecord(g_evJoin1, g_s2);

    // hop-0 chain (table 0 only)
    k_init_ua<<<BATCH + NC * BATCH, 192>>>(ques, ac, Bt);
    k_matvec<<<dim3(12, 9, EK), 256>>>(U, V);
    k_vred<<<216, 256>>>();
    k_gscore<<<dim3(NMEM / 8, BATCH), 256>>>(subj, rel, obj, A);
    k_renorm<<<NVEC * BATCH, NMEM>>>();

    cudaStreamWaitEvent(0, g_evJoin0, 0);          // need table-1 E
    k_oacc<<<dim3(BATCH, MCH, 2), 192>>>(0);
    k_update<<<(NVEC * BATCH * D4 + 255) / 256, 256>>>();

    // hop 1
    k_matvec<<<dim3(12, 9, EK), 256>>>(U, V);
    k_vred<<<216, 256>>>();
    k_scores<<<dim3(NMEM / 16, BATCH), 256>>>(0);
    k_renorm<<<NVEC * BATCH, NMEM>>>();

    cudaStreamWaitEvent(0, g_evJoin1, 0);          // need table-2 E
    k_oacc<<<dim3(BATCH, MCH, 2), 192>>>(1);
    k_update<<<(NVEC * BATCH * D4 + 255) / 256, 256>>>();

    k_qw<<<24, 256>>>(W);
    k_pred<<<dim3(BATCH, NC), 256>>>(out);
}

// round 16
// speedup vs baseline: 1.0518x; 1.0518x over previous
#include <cuda_runtime.h>
#include <math.h>

#define BATCH 32
#define NMEM 512
#define NW 8
#define QL 32
#define NC 8
#define CL 8
#define VOCAB 50000
#define EM 256
#define D 768
#define D4 192          // D / 4
#define D2 384          // D / 2
#define NVEC 9          // vec 0 = question, vec 1..8 = answer choices
#define MCH 16          // m-chunks (32 m each) in o-accumulation
#define EK 8            // split-K factor in matvec (e-chunks of 96)
#define VS (NVEC * BATCH * D)   // one vec-set in floats

// ---------------- device scratch (static: no allocations allowed) ----------
__device__ float g_E[2 * BATCH * NMEM * D];        // 100MB: tables 1,2 (slot = t-1)
__device__ float g_ua[NVEC * BATCH * D];           // rows: r = v*32+b  (u then a)
__device__ float g_vec[NVEC * BATCH * D];          // reduced Uu / Va
__device__ float g_vp[EK * NVEC * BATCH * D];      // matvec split-K partials
__device__ float g_sc[NVEC * BATCH * NMEM];        // scores, then p in place
__device__ float g_op[MCH * NVEC * BATCH * D];     // partial o sums
__device__ float g_o[NVEC * BATCH * D];            // o_q (v=0), o_a (v=1..8)
__device__ float g_qw[BATCH * D];                  // o_q^T W

// ---------------- kernels ---------------------------------------------------

// Materialize E for one table (slot z, table z+1).
// 192 threads: f = tid/64 field, d4 = tid%64 float4 lane; 8 LDG.128 per thread.
__global__ void __launch_bounds__(192) k_embed(
        const int* __restrict__ subj, const int* __restrict__ rel,
        const int* __restrict__ obj, const float* __restrict__ A, int z) {
    __shared__ int sidx[24];
    int m = blockIdx.x, b = blockIdx.y;
    int tid = threadIdx.x;
    if (tid < 24) {
        const int* src = (tid < 8) ? subj : (tid < 16 ? rel : obj);
        sidx[tid] = __ldg(src + (b * NMEM + m) * NW + (tid & 7));
    }
    __syncthreads();
    int f = tid >> 6;            // 0,1,2
    int d4 = tid & 63;           // 0..63
    const float4* tab4 = (const float4*)(A + (size_t)(z + 1) * VOCAB * EM);
    float4 acc = make_float4(0.f, 0.f, 0.f, 0.f);
#pragma unroll
    for (int w = 0; w < NW; w++) {
        float4 v = __ldg(tab4 + (size_t)sidx[f * NW + w] * 64 + d4);
        acc.x += v.x; acc.y += v.y; acc.z += v.z; acc.w += v.w;
    }
    float4* e4 = (float4*)(g_E + ((size_t)(z * BATCH + b) * NMEM + m) * D);
    e4[f * 64 + d4] = acc;
}

// Fused hop-0 scores: gather table 0, field-at-a-time, coalesced lane mapping.
__global__ void __launch_bounds__(256, 6) k_gscore(
        const int* __restrict__ subj, const int* __restrict__ rel,
        const int* __restrict__ obj, const float* __restrict__ A) {
    __shared__ __align__(16) float sv[NVEC * D];   // 27 KB
    __shared__ int sidx[8 * 24];
    int b = blockIdx.y, mc = blockIdx.x;           // 8 m per block
    for (int i = threadIdx.x; i < NVEC * D; i += 256) {
        int v = i / D, d = i - v * D;
        sv[i] = g_vec[(size_t)(v * BATCH + b) * D + d];
    }
    if (threadIdx.x < 192) {
        int m_l = threadIdx.x / 24, which = threadIdx.x % 24;
        int f = which >> 3, w = which & 7;
        const int* src = (f == 0) ? subj : (f == 1 ? rel : obj);
        sidx[threadIdx.x] = __ldg(src + (size_t)(b * NMEM + mc * 8 + m_l) * NW + w);
    }
    __syncthreads();
    int warp = threadIdx.x >> 5, lane = threadIdx.x & 31;
    int m = mc * 8 + warp;
    const int* idx = &sidx[warp * 24];
    const float4* T4 = (const float4*)A;           // table 0

    float acc[NVEC];
#pragma unroll
    for (int v = 0; v < NVEC; v++) acc[v] = 0.f;

#pragma unroll
    for (int f = 0; f < 3; f++) {
        float4 s0 = make_float4(0.f, 0.f, 0.f, 0.f);
        float4 s1 = make_float4(0.f, 0.f, 0.f, 0.f);
#pragma unroll
        for (int w = 0; w < NW; w++) {
            const float4* r4 = T4 + (size_t)idx[f * 8 + w] * 64;
            float4 x0 = __ldg(r4 + lane);
            float4 x1 = __ldg(r4 + 32 + lane);
            s0.x += x0.x; s0.y += x0.y; s0.z += x0.z; s0.w += x0.w;
            s1.x += x1.x; s1.y += x1.y; s1.z += x1.z; s1.w += x1.w;
        }
#pragma unroll
        for (int v = 0; v < NVEC; v++) {
            const float4* s4 = (const float4*)&sv[v * D + f * EM];
            float4 a0 = s4[lane], a1 = s4[32 + lane];
            acc[v] += s0.x * a0.x + s0.y * a0.y + s0.z * a0.z + s0.w * a0.w
                    + s1.x * a1.x + s1.y * a1.y + s1.z * a1.z + s1.w * a1.w;
        }
    }
#pragma unroll
    for (int v = 0; v < NVEC; v++) {
        float x = acc[v];
#pragma unroll
        for (int off = 16; off; off >>= 1)
            x += __shfl_down_sync(0xffffffffu, x, off);
        if (lane == 0)
            g_sc[(size_t)(v * BATCH + b) * NMEM + m] = x;
    }
}

// u[b] = sum_q B[ques];  a[c][b] = sum_w B[answerChoices]  (float4, 192 thr)
__global__ void k_init_ua(const int* __restrict__ ques, const int* __restrict__ ac,
                          const float* __restrict__ Bt) {
    int v = blockIdx.x;            // 0..31 = u rows, 32..287 = a rows (r = 32+c*32+b)
    int d4 = threadIdx.x;          // 0..191
    const float4* B4 = (const float4*)Bt;
    float4 acc = make_float4(0.f, 0.f, 0.f, 0.f);
    if (v < BATCH) {
        for (int q = 0; q < QL; q++) {
            int row = __ldg(ques + v * QL + q);
            float4 x = __ldg(B4 + (size_t)row * D4 + d4);
            acc.x += x.x; acc.y += x.y; acc.z += x.z; acc.w += x.w;
        }
    } else {
        int idx = v - BATCH;
        int c = idx >> 5, b = idx & 31;
        for (int w = 0; w < CL; w++) {
            int row = __ldg(ac + (b * NC + c) * CL + w);
            float4 x = __ldg(B4 + (size_t)row * D4 + d4);
            acc.x += x.x; acc.y += x.y; acc.z += x.z; acc.w += x.w;
        }
    }
    ((float4*)g_ua)[(size_t)v * D4 + d4] = acc;
}

// split-K matvec partial, register-tiled 4r x 2c per thread.
// g_vp[ek][r][d] = sum_{e in chunk of 96} X[r][e] * M[d][e]
// grid (12 col-tiles of 64, 9 row-tiles of 32, EK)
__global__ void __launch_bounds__(256, 6) k_matvec(
        const float* __restrict__ U, const float* __restrict__ V) {
    __shared__ float sX[32][33];
    __shared__ float sM[64][33];
    int ct = blockIdx.x;           // 0..11 (64 cols)
    int rt = blockIdx.y;           // 0..8  (32 rows)
    int ek = blockIdx.z;           // 0..EK-1 (96 e)
    const float* M = (rt == 0) ? U : V;
    int tx = threadIdx.x & 31, ty = threadIdx.x >> 5;   // 32 x 8
    float acc[4][2];
#pragma unroll
    for (int i = 0; i < 4; i++) { acc[i][0] = 0.f; acc[i][1] = 0.f; }
    int eBeg = ek * (D / EK), eEnd = eBeg + (D / EK);
    for (int e0 = eBeg; e0 < eEnd; e0 += 32) {
#pragma unroll
        for (int i = 0; i < 4; i++) {
            int row = ty * 4 + i;
            sX[row][tx] = g_ua[(size_t)(rt * 32 + row) * D + e0 + tx];
        }
#pragma unroll
        for (int i = 0; i < 8; i++) {
            int col = ty * 8 + i;
            sM[col][tx] = __ldg(M + (size_t)(ct * 64 + col) * D + e0 + tx);
        }
        __syncthreads();
#pragma unroll
        for (int e = 0; e < 32; e++) {
            float m0 = sM[tx][e], m1 = sM[tx + 32][e];
#pragma unroll
            for (int i = 0; i < 4; i++) {
                float xv = sX[ty * 4 + i][e];
                acc[i][0] += xv * m0;
                acc[i][1] += xv * m1;
            }
        }
        __syncthreads();
    }
    float* vp = g_vp + (size_t)ek * VS;
#pragma unroll
    for (int i = 0; i < 4; i++) {
        size_t row = rt * 32 + ty * 4 + i;
        vp[row * D + ct * 64 + tx]      = acc[i][0];
        vp[row * D + ct * 64 + 32 + tx] = acc[i][1];
    }
}

// reduce split-K partials: g_vec = sum_ek g_vp[ek]
__global__ void k_vred() {
    const int S = NVEC * BATCH * D4;       // float4 units (55296)
    int i = blockIdx.x * 256 + threadIdx.x;
    if (i >= S) return;
    const float4* vp4 = (const float4*)g_vp;
    float4 r = vp4[i];
#pragma unroll
    for (int k = 1; k < EK; k++) {
        float4 x = vp4[(size_t)k * S + i];
        r.x += x.x; r.y += x.y; r.z += x.z; r.w += x.w;
    }
    ((float4*)g_vec)[i] = r;
}

// hop-1 scores from materialized E (slot 0): 2 m per warp, float4 loads
__global__ void __launch_bounds__(256, 6) k_scores(int slot) {
    __shared__ __align__(16) float4 sv4[NVEC * D4];   // 27 KB
    int b = blockIdx.y;
    const float4* gv4 = (const float4*)g_vec;
    for (int i = threadIdx.x; i < NVEC * D4; i += 256) {
        int v = i / D4, d4 = i - v * D4;
        sv4[i] = gv4[(size_t)(v * BATCH + b) * D4 + d4];
    }
    __syncthreads();
    int warp = threadIdx.x >> 5, lane = threadIdx.x & 31;
    int m0 = blockIdx.x * 16 + warp * 2;
    const float4* e0 = (const float4*)(g_E + ((size_t)(slot * BATCH + b) * NMEM + m0) * D);
    const float4* e1 = e0 + D4;
    float acc[NVEC][2];
#pragma unroll
    for (int v = 0; v < NVEC; v++) { acc[v][0] = 0.f; acc[v][1] = 0.f; }
#pragma unroll
    for (int k = 0; k < 6; k++) {
        int d4 = lane + 32 * k;
        float4 x0 = __ldg(e0 + d4);
        float4 x1 = __ldg(e1 + d4);
#pragma unroll
        for (int v = 0; v < NVEC; v++) {
            float4 s = sv4[v * D4 + d4];
            acc[v][0] += x0.x * s.x + x0.y * s.y + x0.z * s.z + x0.w * s.w;
            acc[v][1] += x1.x * s.x + x1.y * s.y + x1.z * s.z + x1.w * s.w;
        }
    }
#pragma unroll
    for (int v = 0; v < NVEC; v++) {
#pragma unroll
        for (int i = 0; i < 2; i++) {
            float x = acc[v][i];
#pragma unroll
            for (int off = 16; off; off >>= 1)
                x += __shfl_down_sync(0xffffffffu, x, off);
            if (lane == 0)
                g_sc[(size_t)(v * BATCH + b) * NMEM + m0 + i] = x;
        }
    }
}

// block reduce over 512 threads via shuffles: mode 0 sum, 1 max, 2 min
__device__ __forceinline__ float bred512(float v, int mode, float* sw) {
    int lane = threadIdx.x & 31, w = threadIdx.x >> 5;
#pragma unroll
    for (int off = 16; off; off >>= 1) {
        float o = __shfl_xor_sync(0xffffffffu, v, off);
        v = (mode == 0) ? v + o : (mode == 1) ? fmaxf(v, o) : fminf(v, o);
    }
    if (lane == 0) sw[w] = v;
    __syncthreads();
    if (w == 0) {
        float x;
        if (mode == 0)      x = (lane < 16) ? sw[lane] : 0.f;
        else if (mode == 1) x = (lane < 16) ? sw[lane] : -INFINITY;
        else                x = (lane < 16) ? sw[lane] : INFINITY;
#pragma unroll
        for (int off = 16; off; off >>= 1) {
            float o = __shfl_xor_sync(0xffffffffu, x, off);
            x = (mode == 0) ? x + o : (mode == 1) ? fmaxf(x, o) : fminf(x, o);
        }
        if (lane == 0) sw[0] = x;
    }
    __syncthreads();
    float r = sw[0];
    __syncthreads();
    return r;
}

// merged renorm: rows 0..31 = question variant, 32..287 = answer variant
__global__ void k_renorm() {
    __shared__ float sw[16];
    int r = blockIdx.x;            // 0..287, row = v*BATCH+b
    int m = threadIdx.x;
    size_t base = (size_t)r * NMEM;
    float s = g_sc[base + m];
    float mx = bred512(s, 1, sw);
    float se = bred512(expf(s - mx), 0, sw);
    float p = s - mx - logf(se);
    if (r < BATCH) {
        float mn = bred512(p, 2, sw);
        p -= mn;
        float nrm = bred512(fabsf(p + 1e-8f), 0, sw);
        g_sc[base + m] = p / nrm;
    } else {
        float nrm = bred512(fabsf(p), 0, sw);
        float p2 = (nrm == 0.f) ? (p + 1.f) : p;
        float nrm2 = bred512(fabsf(p2), 0, sw);
        g_sc[base + m] = p2 / nrm2;
    }
}

// partial o sums: g_op[mc][v][b][:] = sum_{m in 32-chunk} p[v][b][m] * E[slot][b][m][:]
// grid (b, mc); 192 threads, each owns one float4 of D
__global__ void __launch_bounds__(192) k_oacc(int slot) {
    __shared__ float sp[NVEC * 32];
    int b = blockIdx.x, mc = blockIdx.y;
    for (int i = threadIdx.x; i < NVEC * 32; i += 192) {
        int v = i >> 5, ml = i & 31;
        sp[i] = g_sc[(size_t)(v * BATCH + b) * NMEM + mc * 32 + ml];
    }
    __syncthreads();
    int d4 = threadIdx.x;          // 0..191
    const float4* e = (const float4*)(g_E + ((size_t)(slot * BATCH + b) * NMEM + mc * 32) * D);
    float4 acc[NVEC];
#pragma unroll
    for (int v = 0; v < NVEC; v++) acc[v] = make_float4(0.f, 0.f, 0.f, 0.f);
#pragma unroll 4
    for (int ml = 0; ml < 32; ml++) {
        float4 ev = __ldg(e + (size_t)ml * D4 + d4);
#pragma unroll
        for (int v = 0; v < NVEC; v++) {
            float p = sp[v * 32 + ml];
            acc[v].x += ev.x * p; acc[v].y += ev.y * p;
            acc[v].z += ev.z * p; acc[v].w += ev.w * p;
        }
    }
    float4* op4 = (float4*)g_op;
#pragma unroll
    for (int v = 0; v < NVEC; v++)
        op4[(size_t)((mc * NVEC + v) * BATCH + b) * D4 + d4] = acc[v];
}

// o = sum of MCH partials; u/a += o
__global__ void k_update() {
    const int S = NVEC * BATCH * D4;       // in float4 units
    int i = blockIdx.x * 256 + threadIdx.x;
    if (i >= S) return;
    const float4* op4 = (const float4*)g_op;
    float4 o = make_float4(0.f, 0.f, 0.f, 0.f);
#pragma unroll
    for (int k = 0; k < MCH; k++) {
        float4 x = op4[(size_t)k * S + i];
        o.x += x.x; o.y += x.y; o.z += x.z; o.w += x.w;
    }
    ((float4*)g_o)[i] = o;
    float4 u = ((float4*)g_ua)[i];
    u.x += o.x; u.y += o.y; u.z += o.z; u.w += o.w;
    ((float4*)g_ua)[i] = u;
}

// qw[b][e] = sum_d o_q[b][d] * W[d][e]   (tiled: W read once)
__global__ void k_qw(const float* __restrict__ W) {
    __shared__ float sQ[32][33];
    __shared__ float sW[32][33];
    int et = blockIdx.x;           // 0..23
    int tx = threadIdx.x & 31, ty = threadIdx.x >> 5;   // 32 x 8
    float acc[4] = {0.f, 0.f, 0.f, 0.f};
    for (int d0 = 0; d0 < D; d0 += 32) {
#pragma unroll
        for (int i = 0; i < 4; i++) {
            int row = ty * 4 + i;
            sQ[row][tx] = g_o[(size_t)row * D + d0 + tx];          // b = row
            sW[row][tx] = __ldg(W + (size_t)(d0 + row) * D + et * 32 + tx);
        }
        __syncthreads();
#pragma unroll
        for (int k = 0; k < 32; k++) {
            float wv = sW[k][tx];
#pragma unroll
            for (int i = 0; i < 4; i++) acc[i] += sQ[ty * 4 + i][k] * wv;
        }
        __syncthreads();
    }
#pragma unroll
    for (int i = 0; i < 4; i++)
        g_qw[(size_t)(ty * 4 + i) * D + et * 32 + tx] = acc[i];
}

// pred[b][c] = qW[b] . o_a[c][b]
__global__ void k_pred(float* __restrict__ out) {
    __shared__ float sh[256];
    int b = blockIdx.x, c = blockIdx.y;
    int t = threadIdx.x;
    const float* q = g_qw + (size_t)b * D;
    const float* oa = g_o + (size_t)((1 + c) * BATCH + b) * D;
    float acc = 0.f;
    for (int e = t; e < D; e += 256) acc += q[e] * oa[e];
    sh[t] = acc;
    __syncthreads();
    for (int s = 128; s > 0; s >>= 1) {
        if (t < s) sh[t] += sh[t + s];
        __syncthreads();
    }
    if (t == 0) out[b * NC + c] = sh[0];
}

// ---------------- launch ----------------------------------------------------
static cudaStream_t g_s2 = 0;
static cudaEvent_t  g_evFork = 0, g_evJoin0 = 0, g_evJoin1 = 0;

extern "C" void kernel_launch(void* const* d_in, const int* in_sizes, int n_in,
                              void* d_out, int out_size) {
    const int*   subj = (const int*)d_in[0];
    const int*   rel  = (const int*)d_in[1];
    const int*   obj  = (const int*)d_in[2];
    const int*   ques = (const int*)d_in[3];
    const int*   ac   = (const int*)d_in[4];
    const float* A    = (const float*)d_in[5];
    const float* Bt   = (const float*)d_in[6];
    const float* U    = (const float*)d_in[7];
    const float* V    = (const float*)d_in[8];
    const float* W    = (const float*)d_in[9];
    float* out = (float*)d_out;

    if (!g_s2) {
        cudaStreamCreateWithFlags(&g_s2, cudaStreamNonBlocking);
        cudaEventCreateWithFlags(&g_evFork, cudaEventDisableTiming);
        cudaEventCreateWithFlags(&g_evJoin0, cudaEventDisableTiming);
        cudaEventCreateWithFlags(&g_evJoin1, cudaEventDisableTiming);
    }

    // Fork: embed table 1 then table 2 on the side stream.
    cudaEventRecord(g_evFork, 0);
    cudaStreamWaitEvent(g_s2, g_evFork, 0);
    k_embed<<<dim3(NMEM, BATCH), 192, 0, g_s2>>>(subj, rel, obj, A, 0);
    cudaEventRecord(g_evJoin0, g_s2);
    k_embed<<<dim3(NMEM, BATCH), 192, 0, g_s2>>>(subj, rel, obj, A, 1);
    cudaEventRecord(g_evJoin1, g_s2);

    // hop-0 chain (table 0 only)
    k_init_ua<<<BATCH + NC * BATCH, 192>>>(ques, ac, Bt);
    k_matvec<<<dim3(12, 9, EK), 256>>>(U, V);
    k_vred<<<216, 256>>>();
    k_gscore<<<dim3(NMEM / 8, BATCH), 256>>>(subj, rel, obj, A);
    k_renorm<<<NVEC * BATCH, NMEM>>>();

    cudaStreamWaitEvent(0, g_evJoin0, 0);          // need table-1 E
    k_oacc<<<dim3(BATCH, MCH), 192>>>(0);
    k_update<<<(NVEC * BATCH * D4 + 255) / 256, 256>>>();

    // hop 1
    k_matvec<<<dim3(12, 9, EK), 256>>>(U, V);
    k_vred<<<216, 256>>>();
    k_scores<<<dim3(NMEM / 16, BATCH), 256>>>(0);
    k_renorm<<<NVEC * BATCH, NMEM>>>();

    cudaStreamWaitEvent(0, g_evJoin1, 0);          // need table-2 E
    k_oacc<<<dim3(BATCH, MCH), 192>>>(1);
    k_update<<<(NVEC * BATCH * D4 + 255) / 256, 256>>>();

    k_qw<<<24, 256>>>(W);
    k_pred<<<dim3(BATCH, NC), 256>>>(out);
}